// round 7
// baseline (speedup 1.0000x reference)
#include <cuda_runtime.h>

// Pfaffian of 128x128 skew-symmetric submatrices gathered from a 256x256
// skew matrix F_full (strict lower triangle F, row-major tril order:
// F_full[i][j] = F[i*(i-1)/2 + j] for i > j).
//
// One CTA per batch element. A lives in shared memory (128 x 129 pad).
// Parlett-Reid LTL^T without pivoting, 64 sequential rank-2 updates.
//
// NUMERICS (round 6): bit-match XLA GPU codegen of the reference:
//   - XLA algebraic simplifier rewrites  row/pivot  ->  row * (1/pivot)
//     with ONE IEEE division for the reciprocal, then plain multiplies.
//   - The update (A + tau_i*col_j) - col_i*tau_j is FMA-contracted as
//     fma(-col_i, tau_j, fma(tau_i, col_j, A))   [confirmed direction by R5's
//     7x error drop; division handling is the remaining knob]

#define N128 128
#define LDA  129   // pad: stride 129 == 1 mod 32 -> conflict-free column access

extern __shared__ float smem[];

__global__ __launch_bounds__(N128, 1)
void pfaffian_kernel(const float* __restrict__ x,
                     const float* __restrict__ F,
                     float* __restrict__ out)
{
    float* A    = smem;                         // 128*129 floats
    float* sx   = A + N128 * LDA;               // 128
    float* tau  = sx + N128;                    // 128
    float* col  = tau + N128;                   // 128
    int*   idx  = (int*)(col + N128);           // 128

    const int b = blockIdx.x;
    const int t = threadIdx.x;

    // ---- load x row ----
    sx[t] = x[b * N128 + t];
    __syncthreads();

    // ---- occupancy ranks: occ = [x>0 (slots 0..127), x<=0 (slots 128..255)],
    //      idx = sorted positions of the 128 set slots ----
    {
        const bool mine = sx[t] > 0.0f;
        int cntBefore = 0, totPos = 0;
        #pragma unroll 8
        for (int l = 0; l < N128; ++l) {
            const bool p = sx[l] > 0.0f;   // broadcast LDS
            totPos += p ? 1 : 0;
            if (l < t) cntBefore += p ? 1 : 0;
        }
        const int pos = mine ? cntBefore : (totPos + (t - cntBefore));
        idx[pos] = mine ? t : (N128 + t);
    }
    __syncthreads();

    // ---- gather A[r][c] = F_full[idx[r], idx[c]] (exact, no rounding) ----
    {
        const int jj   = idx[t];
        const int jtri = jj * (jj - 1) / 2;
        #pragma unroll 4
        for (int r = 0; r < N128; ++r) {
            const int i = idx[r];
            float v;
            if (i > jj)      v =  __ldg(&F[i * (i - 1) / 2 + jj]);
            else if (i < jj) v = -__ldg(&F[jtri + i]);
            else             v = 0.0f;
            A[r * LDA + t] = v;
        }
    }
    __syncthreads();

    // ---- Parlett-Reid elimination: 64 steps, pf = prod pivots ----
    float pf = 1.0f;
    for (int step = 0; step < N128 / 2; ++step) {
        const int k = 2 * step;

        // snapshot: pivot (broadcast); tau = row_k * (1/pivot) where the
        // reciprocal is ONE IEEE division (XLA scalar-divisor rewrite);
        // col = column k+1 (stride 129, conflict-free)
        const float pivot = A[k * LDA + (k + 1)];
        const float invp  = __fdiv_rn(1.0f, pivot);
        if (t > k + 1) {
            tau[t] = __fmul_rn(A[k * LDA + t], invp);
            col[t] = A[t * LDA + (k + 1)];
        }
        if (t == 0) pf = __fmul_rn(pf, pivot);
        __syncthreads();

        // rank-2 update, thread t owns row t.
        // Contracted rounding: fma(-col_i, tau_j, fma(tau_i, col_j, A))
        if (t > k + 1) {
            const float tr = tau[t];
            const float cr = col[t];
            float* __restrict__ Ar = &A[t * LDA];
            #pragma unroll 4
            for (int c = k + 2; c < N128; ++c) {
                const float inner = __fmaf_rn(tr, col[c], Ar[c]);
                Ar[c] = __fmaf_rn(-cr, tau[c], inner);
            }
        }
        __syncthreads();
    }

    if (t == 0) out[b] = pf;
}

extern "C" void kernel_launch(void* const* d_in, const int* in_sizes, int n_in,
                              void* d_out, int out_size)
{
    const float* x = (const float*)d_in[0];   // (B, 128) fp32
    const float* F = (const float*)d_in[1];   // 256*255/2 fp32
    float* out = (float*)d_out;               // (B,) fp32

    const int B = in_sizes[0] / N128;

    const size_t shmem = (size_t)(N128 * LDA + 4 * N128) * sizeof(float);

    cudaFuncSetAttribute(pfaffian_kernel,
                         cudaFuncAttributeMaxDynamicSharedMemorySize,
                         (int)shmem);

    pfaffian_kernel<<<B, N128, shmem>>>(x, F, out);
}

// round 9
// speedup vs baseline: 2.9158x; 2.9158x over previous
#include <cuda_runtime.h>

// Pfaffian of 128x128 skew-symmetric submatrices gathered from a 256x256
// skew matrix F_full (strict lower tri F, row-major: F_full[i][j]=F[i(i-1)/2+j], i>j).
//
// One CTA / batch element; A in shared (128 x 132, float4-aligned rows).
// Parlett-Reid LTL^T, 64 sequential rank-2 updates, bit-exact vs XLA:
//   tau = row_k * (1/pivot)        (ONE __fdiv_rn reciprocal, then __fmul_rn)
//   A'  = fma(-col_i, tau_j, fma(tau_i, col_j, A))   (contracted, __fmaf_rn)
//   pf  = sequential __fmul_rn of pivots
// 512 threads: 4 threads per row (q = t>>7), interleaved float4 chunks.

#define N128 128
#define LDA  132   // multiple of 4 for float4 rows; column access 8-way (rare)
#define NTHR 512

extern __shared__ float smem[];

__global__ __launch_bounds__(NTHR, 1)
void pfaffian_kernel(const float* __restrict__ x,
                     const float* __restrict__ F,
                     float* __restrict__ out)
{
    float* A    = smem;                          // 128*132
    float* tau  = A + N128 * LDA;                // 128 (16B aligned)
    float* col  = tau + N128;                    // 128
    float* sx   = col + N128;                    // 128
    int*   idx  = (int*)(sx + N128);             // 128

    const int b = blockIdx.x;
    const int t = threadIdx.x;
    const int r = t & 127;    // row owned in update phase
    const int q = t >> 7;     // chunk-interleave group 0..3

    // ---- load x row ----
    if (t < N128) sx[t] = x[b * N128 + t];
    __syncthreads();

    // ---- occupancy ranks: occ=[x>0 | x<=0], idx = sorted set-slot positions ----
    if (t < N128) {
        const bool mine = sx[t] > 0.0f;
        int cntBefore = 0, totPos = 0;
        #pragma unroll 8
        for (int l = 0; l < N128; ++l) {
            const bool p = sx[l] > 0.0f;
            totPos += p ? 1 : 0;
            if (l < t) cntBefore += p ? 1 : 0;
        }
        const int pos = mine ? cntBefore : (totPos + (t - cntBefore));
        idx[pos] = mine ? t : (N128 + t);
    }
    __syncthreads();

    // ---- gather A[rr][c] = F_full[idx[rr], idx[c]] (exact) ----
    {
        const int c    = t & 127;          // fixed column per thread
        const int jj   = idx[c];
        const int jtri = jj * (jj - 1) / 2;
        #pragma unroll 4
        for (int rr = (t >> 7); rr < N128; rr += 4) {
            const int i = idx[rr];
            float v;
            if (i > jj)      v =  __ldg(&F[i * (i - 1) / 2 + jj]);
            else if (i < jj) v = -__ldg(&F[jtri + i]);
            else             v = 0.0f;
            A[rr * LDA + c] = v;
        }
    }
    __syncthreads();

    // ---- Parlett-Reid elimination: 64 steps ----
    float pf = 1.0f;
    for (int step = 0; step < N128 / 2; ++step) {
        const int k = 2 * step;

        // snapshot (threads 0..127): tau = row_k * (1/pivot), col = column k+1
        if (t < N128) {
            const float pivot = A[k * LDA + (k + 1)];
            const float invp  = __fdiv_rn(1.0f, pivot);
            tau[t] = __fmul_rn(A[k * LDA + t], invp);   // all t; t<=k+1 unused
            col[t] = A[t * LDA + (k + 1)];
            if (t == 0) pf = __fmul_rn(pf, pivot);
        }
        __syncthreads();

        // rank-2 update: thread (r,q) does float4 chunks c4 = cc0+q, +4, ...
        if (r > k + 1) {
            const float tr = tau[r];
            const float cr = col[r];
            float4* __restrict__ Arow = (float4*)(A + r * LDA);
            const float4* __restrict__ tau4 = (const float4*)tau;
            const float4* __restrict__ col4 = (const float4*)col;
            const int cc0 = (k + 2) >> 2;
            const int klim = k + 2;
            for (int c4 = cc0 + q; c4 < N128 / 4; c4 += 4) {
                float4 a  = Arow[c4];
                const float4 tv = tau4[c4];   // broadcast
                const float4 cv = col4[c4];   // broadcast
                const int cb = c4 << 2;
                // contracted per-element rounding, identical to reference
                const float n0 = __fmaf_rn(-cr, tv.x, __fmaf_rn(tr, cv.x, a.x));
                const float n1 = __fmaf_rn(-cr, tv.y, __fmaf_rn(tr, cv.y, a.y));
                const float n2 = __fmaf_rn(-cr, tv.z, __fmaf_rn(tr, cv.z, a.z));
                const float n3 = __fmaf_rn(-cr, tv.w, __fmaf_rn(tr, cv.w, a.w));
                // only the first chunk can be partial; discarded lanes keep old A
                a.x = (cb + 0 >= klim) ? n0 : a.x;
                a.y = (cb + 1 >= klim) ? n1 : a.y;
                a.z = (cb + 2 >= klim) ? n2 : a.z;
                a.w = (cb + 3 >= klim) ? n3 : a.w;
                Arow[c4] = a;
            }
        }
        __syncthreads();
    }

    if (t == 0) out[b] = pf;
}

extern "C" void kernel_launch(void* const* d_in, const int* in_sizes, int n_in,
                              void* d_out, int out_size)
{
    const float* x = (const float*)d_in[0];   // (B, 128) fp32
    const float* F = (const float*)d_in[1];   // 256*255/2 fp32
    float* out = (float*)d_out;               // (B,) fp32

    const int B = in_sizes[0] / N128;

    // A (128*132) + tau/col/sx (3*128) + idx (128)
    const size_t shmem = (size_t)(N128 * LDA + 4 * N128) * sizeof(float);

    cudaFuncSetAttribute(pfaffian_kernel,
                         cudaFuncAttributeMaxDynamicSharedMemorySize,
                         (int)shmem);

    pfaffian_kernel<<<B, NTHR, shmem>>>(x, F, out);
}

// round 10
// speedup vs baseline: 3.7764x; 1.2951x over previous
#include <cuda_runtime.h>

// Pfaffian of 128x128 skew-symmetric submatrices gathered from a 256x256
// skew matrix F_full (strict lower tri F: F_full[i][j]=F[i(i-1)/2+j], i>j).
//
// One CTA / batch element; A in shared (128 x 132, float4 rows).
// Parlett-Reid LTL^T, TWO elimination steps per barrier pair (32 blocks).
// Bit-exact vs XLA codegen of the reference:
//   tau  = where(mask) row_k * (1/pivot)   (one __fdiv_rn, then __fmul_rn)
//   A'   = fma(-col_r, tau_c, fma(tau_r, col_c, A))   (contracted)
//   masked entries are EXACT zeros -> fma-with-zero no-op, same as reference
//   pf   = sequential __fmul_rn of pivots
// Both updates of a block are applied back-to-back in registers (the
// intermediate matrix is never materialized; rounding chain identical).

#define N128 128
#define LDA  132
#define NTHR 512

extern __shared__ float smem[];

__global__ __launch_bounds__(NTHR, 1)
void pfaffian_kernel(const float* __restrict__ x,
                     const float* __restrict__ F,
                     float* __restrict__ out)
{
    float* A     = smem;                          // 128*132
    float* tau1  = A + N128 * LDA;                // 128 (16B aligned)
    float* col1  = tau1 + N128;                   // 128
    float* tau2  = col1 + N128;                   // 128
    float* col2  = tau2 + N128;                   // 128
    float* sx    = col2 + N128;                   // 128
    int*   idx   = (int*)(sx + N128);             // 128

    const int b = blockIdx.x;
    const int t = threadIdx.x;
    const int r = t & 127;    // row owned in update phase
    const int q = t >> 7;     // chunk-interleave group 0..3

    // ---- load x row ----
    if (t < N128) sx[t] = x[b * N128 + t];
    __syncthreads();

    // ---- occupancy ranks ----
    if (t < N128) {
        const bool mine = sx[t] > 0.0f;
        int cntBefore = 0, totPos = 0;
        #pragma unroll 8
        for (int l = 0; l < N128; ++l) {
            const bool p = sx[l] > 0.0f;
            totPos += p ? 1 : 0;
            if (l < t) cntBefore += p ? 1 : 0;
        }
        const int pos = mine ? cntBefore : (totPos + (t - cntBefore));
        idx[pos] = mine ? t : (N128 + t);
    }
    __syncthreads();

    // ---- gather A[rr][c] = F_full[idx[rr], idx[c]] ----
    {
        const int c    = t & 127;
        const int jj   = idx[c];
        const int jtri = jj * (jj - 1) / 2;
        #pragma unroll 4
        for (int rr = (t >> 7); rr < N128; rr += 4) {
            const int i = idx[rr];
            float v;
            if (i > jj)      v =  __ldg(&F[i * (i - 1) / 2 + jj]);
            else if (i < jj) v = -__ldg(&F[jtri + i]);
            else             v = 0.0f;
            A[rr * LDA + c] = v;
        }
    }
    __syncthreads();

    // ---- 32 blocks of 2 elimination steps each ----
    float pf = 1.0f;
    for (int blk = 0; blk < N128 / 4; ++blk) {
        const int k = 4 * blk;   // first step pivot row; second is k+2

        if (t < N128) {
            // Phase S: snapshot step-k quantities (pre-update matrix)
            const float pivot1 = A[k * LDA + (k + 1)];
            const float invp1  = __fdiv_rn(1.0f, pivot1);
            const float akt    = A[k * LDA + t];
            const float atk1   = A[t * LDA + (k + 1)];
            const float ak2t   = A[(k + 2) * LDA + t];
            const float atk3   = A[t * LDA + (k + 3)];
            const float ak2k3  = A[(k + 2) * LDA + (k + 3)];
            const float t1 = (t > k + 1) ? __fmul_rn(akt, invp1) : 0.0f;
            const float c1 = (t > k + 1) ? atk1 : 0.0f;
            tau1[t] = t1;
            col1[t] = c1;
            asm volatile("bar.sync 1, 128;" ::: "memory");  // warps 0-3 only

            // Phase S2: step-(k+2) quantities from the step-k-updated row/col
            const float t1k2 = tau1[k + 2], t1k3 = tau1[k + 3];
            const float c1k2 = col1[k + 2], c1k3 = col1[k + 3];
            // updated A[k+2][k+3] (computed redundantly by every thread)
            const float pivot2 = __fmaf_rn(-c1k2, t1k3,
                                 __fmaf_rn( t1k2, c1k3, ak2k3));
            const float invp2  = __fdiv_rn(1.0f, pivot2);
            // updated A[k+2][t] and A[t][k+3]
            const float row2    = __fmaf_rn(-c1k2, t1,
                                  __fmaf_rn( t1k2, c1, ak2t));
            const float col2raw = __fmaf_rn(-c1,   t1k3,
                                  __fmaf_rn( t1,   c1k3, atk3));
            tau2[t] = (t > k + 3) ? __fmul_rn(row2, invp2) : 0.0f;
            col2[t] = (t > k + 3) ? col2raw : 0.0f;
            if (t == 0) pf = __fmul_rn(__fmul_rn(pf, pivot1), pivot2);
        }
        __syncthreads();

        // Phase U: apply both rank-2 updates back-to-back in registers.
        // Zero-masked tau/col arrays make boundary elements exact no-ops
        // (identical to the reference's where()-masked updates).
        if (r > k + 1) {
            const float t1r = tau1[r], c1r = col1[r];
            const float t2r = tau2[r], c2r = col2[r];  // 0 for r<=k+3
            float4* __restrict__ Arow = (float4*)(A + r * LDA);
            const float4* __restrict__ t1v4 = (const float4*)tau1;
            const float4* __restrict__ c1v4 = (const float4*)col1;
            const float4* __restrict__ t2v4 = (const float4*)tau2;
            const float4* __restrict__ c2v4 = (const float4*)col2;
            const int cc0 = (k + 2) >> 2;   // == blk
            #pragma unroll 2
            for (int c4 = cc0 + q; c4 < N128 / 4; c4 += 4) {
                float4 a        = Arow[c4];
                const float4 t1v = t1v4[c4];
                const float4 c1v = c1v4[c4];
                const float4 t2v = t2v4[c4];
                const float4 c2v = c2v4[c4];
                // step k
                const float v1x = __fmaf_rn(-c1r, t1v.x, __fmaf_rn(t1r, c1v.x, a.x));
                const float v1y = __fmaf_rn(-c1r, t1v.y, __fmaf_rn(t1r, c1v.y, a.y));
                const float v1z = __fmaf_rn(-c1r, t1v.z, __fmaf_rn(t1r, c1v.z, a.z));
                const float v1w = __fmaf_rn(-c1r, t1v.w, __fmaf_rn(t1r, c1v.w, a.w));
                // step k+2 (zero-masked where not applicable)
                a.x = __fmaf_rn(-c2r, t2v.x, __fmaf_rn(t2r, c2v.x, v1x));
                a.y = __fmaf_rn(-c2r, t2v.y, __fmaf_rn(t2r, c2v.y, v1y));
                a.z = __fmaf_rn(-c2r, t2v.z, __fmaf_rn(t2r, c2v.z, v1z));
                a.w = __fmaf_rn(-c2r, t2v.w, __fmaf_rn(t2r, c2v.w, v1w));
                Arow[c4] = a;
            }
        }
        __syncthreads();
    }

    if (t == 0) out[b] = pf;
}

extern "C" void kernel_launch(void* const* d_in, const int* in_sizes, int n_in,
                              void* d_out, int out_size)
{
    const float* x = (const float*)d_in[0];   // (B, 128) fp32
    const float* F = (const float*)d_in[1];   // 256*255/2 fp32
    float* out = (float*)d_out;               // (B,) fp32

    const int B = in_sizes[0] / N128;

    // A (128*132) + tau1/col1/tau2/col2/sx (5*128) + idx (128)
    const size_t shmem = (size_t)(N128 * LDA + 6 * N128) * sizeof(float);

    cudaFuncSetAttribute(pfaffian_kernel,
                         cudaFuncAttributeMaxDynamicSharedMemorySize,
                         (int)shmem);

    pfaffian_kernel<<<B, NTHR, shmem>>>(x, F, out);
}

// round 11
// speedup vs baseline: 4.0511x; 1.0728x over previous
#include <cuda_runtime.h>

// Pfaffian of 128x128 skew-symmetric submatrices gathered from a 256x256
// skew matrix F_full (strict lower tri F: F_full[i][j]=F[i(i-1)/2+j], i>j).
//
// One CTA / batch element. Parlett-Reid LTL^T, 2 steps per block, 32 blocks.
// WARP-SPECIALIZED PIPELINE:
//   - snapshot crew (threads 0-127): "head" pass updates only the 4 lines the
//     next block's snapshot needs, then computes next tau/col (2 divisions)
//   - bulk crew (threads 128-639): applies current block's rank-2 pair to the
//     remaining live region, CONCURRENTLY with the snapshot
//   - dead rows/cols (< k+4) are never touched again (trim)
// Bit-exact vs XLA codegen (rel_err == 0.0 lineage):
//   tau = masked row_k * (1/pivot)   (one __fdiv_rn then __fmul_rn)
//   A'  = fma(-col_r, tau_c, fma(tau_r, col_c, A))  (contracted, in step order)
//   pf  = sequential __fmul_rn of pivots

#define N128 128
#define LDA  132
#define NTHR 640
#define NC4  (N128 / 4)

extern __shared__ float smem[];

__device__ __forceinline__ float4 apply2_f4(float4 a, float t1r, float c1r,
                                            float t2r, float c2r,
                                            float4 t1v, float4 c1v,
                                            float4 t2v, float4 c2v)
{
    const float vx = __fmaf_rn(-c1r, t1v.x, __fmaf_rn(t1r, c1v.x, a.x));
    const float vy = __fmaf_rn(-c1r, t1v.y, __fmaf_rn(t1r, c1v.y, a.y));
    const float vz = __fmaf_rn(-c1r, t1v.z, __fmaf_rn(t1r, c1v.z, a.z));
    const float vw = __fmaf_rn(-c1r, t1v.w, __fmaf_rn(t1r, c1v.w, a.w));
    a.x = __fmaf_rn(-c2r, t2v.x, __fmaf_rn(t2r, c2v.x, vx));
    a.y = __fmaf_rn(-c2r, t2v.y, __fmaf_rn(t2r, c2v.y, vy));
    a.z = __fmaf_rn(-c2r, t2v.z, __fmaf_rn(t2r, c2v.z, vz));
    a.w = __fmaf_rn(-c2r, t2v.w, __fmaf_rn(t2r, c2v.w, vw));
    return a;
}

// Compute tau/col for the block starting at row k (steps k, k+2) from A,
// which must already hold all corrections from earlier blocks on the lines
// this reads (rows k, k+2; cols k+1, k+3). Threads 0-127 only.
__device__ __forceinline__ void snapshot_block(const float* __restrict__ A,
                                               int k,
                                               float* __restrict__ tau1,
                                               float* __restrict__ col1,
                                               float* __restrict__ tau2,
                                               float* __restrict__ col2,
                                               int t, float& pf)
{
    const float pivot1 = A[k * LDA + (k + 1)];
    const float invp1  = __fdiv_rn(1.0f, pivot1);
    const float akt    = A[k * LDA + t];
    const float atk1   = A[t * LDA + (k + 1)];
    const float ak2t   = A[(k + 2) * LDA + t];
    const float atk3   = A[t * LDA + (k + 3)];
    const float ak2k3  = A[(k + 2) * LDA + (k + 3)];
    const float t1 = (t > k + 1) ? __fmul_rn(akt, invp1) : 0.0f;
    const float c1 = (t > k + 1) ? atk1 : 0.0f;
    tau1[t] = t1;
    col1[t] = c1;
    asm volatile("bar.sync 1, 128;" ::: "memory");   // warps 0-3 only

    const float t1k2 = tau1[k + 2], t1k3 = tau1[k + 3];
    const float c1k2 = col1[k + 2], c1k3 = col1[k + 3];
    const float pivot2 = __fmaf_rn(-c1k2, t1k3, __fmaf_rn(t1k2, c1k3, ak2k3));
    const float invp2  = __fdiv_rn(1.0f, pivot2);
    const float row2    = __fmaf_rn(-c1k2, t1, __fmaf_rn(t1k2, c1, ak2t));
    const float col2raw = __fmaf_rn(-c1,   t1k3, __fmaf_rn(t1, c1k3, atk3));
    tau2[t] = (t > k + 3) ? __fmul_rn(row2, invp2) : 0.0f;
    col2[t] = (t > k + 3) ? col2raw : 0.0f;
    if (t == 0) pf = __fmul_rn(__fmul_rn(pf, pivot1), pivot2);
}

__global__ __launch_bounds__(NTHR, 1)
void pfaffian_kernel(const float* __restrict__ x,
                     const float* __restrict__ F,
                     float* __restrict__ out)
{
    float* A    = smem;                          // 128*132
    float* bufs = A + N128 * LDA;                // 2 parities * 4 arrays * 128
    float* sx   = bufs + 2 * 4 * N128;           // 128
    int*   idx  = (int*)(sx + N128);             // 128

    const int b = blockIdx.x;
    const int t = threadIdx.x;

    // ---- load x row + occupancy ranks (threads 0-127) ----
    if (t < N128) sx[t] = x[b * N128 + t];
    __syncthreads();
    if (t < N128) {
        const bool mine = sx[t] > 0.0f;
        int cntBefore = 0, totPos = 0;
        #pragma unroll 8
        for (int l = 0; l < N128; ++l) {
            const bool p = sx[l] > 0.0f;
            totPos += p ? 1 : 0;
            if (l < t) cntBefore += p ? 1 : 0;
        }
        const int pos = mine ? cntBefore : (totPos + (t - cntBefore));
        idx[pos] = mine ? t : (N128 + t);
    }
    __syncthreads();

    // ---- gather A[rr][c] = F_full[idx[rr], idx[c]] (640 threads) ----
    {
        const int c    = t % N128;
        const int jj   = idx[c];
        const int jtri = jj * (jj - 1) / 2;
        for (int rr = t / N128; rr < N128; rr += NTHR / N128) {
            const int i = idx[rr];
            float v;
            if (i > jj)      v =  __ldg(&F[i * (i - 1) / 2 + jj]);
            else if (i < jj) v = -__ldg(&F[jtri + i]);
            else             v = 0.0f;
            A[rr * LDA + c] = v;
        }
    }
    __syncthreads();

    // ---- prologue: snapshot block 0 into parity 0 ----
    float pf = 1.0f;
    if (t < N128)
        snapshot_block(A, 0, bufs, bufs + 128, bufs + 256, bufs + 384, t, pf);

    // ---- 31 pipelined iterations: apply block s, snapshot block s+1 ----
    for (int s = 0; s < 31; ++s) {
        __syncthreads();   // orders prev bulk writes + snapshot buffer writes
        const int k = 4 * s;
        float* cur = bufs + (s & 1) * 512;        // parity s
        float* nxt = bufs + ((s + 1) & 1) * 512;  // parity s+1
        float* tau1p = cur;       float* col1p = cur + 128;
        float* tau2p = cur + 256; float* col2p = cur + 384;
        const float4* T1 = (const float4*)tau1p;
        const float4* C1 = (const float4*)col1p;
        const float4* T2 = (const float4*)tau2p;
        const float4* C2 = (const float4*)col2p;

        if (t < N128) {
            // ---- head: update the 4 lines snapshot s+1 needs ----
            // H1: chunk s+1, row r = k+4+t
            {
                const int r = k + 4 + t;
                if (r < N128) {
                    const float t1r = tau1p[r], c1r = col1p[r];
                    const float t2r = tau2p[r], c2r = col2p[r];
                    float4* Ar = (float4*)(A + r * LDA);
                    const int c4 = s + 1;
                    Ar[c4] = apply2_f4(Ar[c4], t1r, c1r, t2r, c2r,
                                       T1[c4], C1[c4], T2[c4], C2[c4]);
                }
            }
            // H2: rows k+4, k+6 for chunks >= s+2
            {
                const int r  = k + 4 + 2 * (t & 1);
                const int c4 = s + 2 + (t >> 1);
                if (c4 < NC4) {
                    const float t1r = tau1p[r], c1r = col1p[r];
                    const float t2r = tau2p[r], c2r = col2p[r];
                    float4* Ar = (float4*)(A + r * LDA);
                    Ar[c4] = apply2_f4(Ar[c4], t1r, c1r, t2r, c2r,
                                       T1[c4], C1[c4], T2[c4], C2[c4]);
                }
            }
            asm volatile("bar.sync 1, 128;" ::: "memory");  // head visible

            // ---- snapshot block s+1 (reads only head-updated lines) ----
            snapshot_block(A, k + 4, nxt, nxt + 128, nxt + 256, nxt + 384,
                           t, pf);
        } else {
            // ---- bulk: remaining live region (disjoint from head lines) ----
            const int u = t - N128;
            const int r = u & 127;
            const int q = u >> 7;
            if (r > k + 3 && r != k + 4 && r != k + 6) {
                const float t1r = tau1p[r], c1r = col1p[r];
                const float t2r = tau2p[r], c2r = col2p[r];
                float4* __restrict__ Ar = (float4*)(A + r * LDA);
                #pragma unroll 4
                for (int c4 = s + 2 + q; c4 < NC4; c4 += 4)
                    Ar[c4] = apply2_f4(Ar[c4], t1r, c1r, t2r, c2r,
                                       T1[c4], C1[c4], T2[c4], C2[c4]);
            }
        }
    }

    if (t == 0) out[b] = pf;
}

extern "C" void kernel_launch(void* const* d_in, const int* in_sizes, int n_in,
                              void* d_out, int out_size)
{
    const float* x = (const float*)d_in[0];   // (B, 128) fp32
    const float* F = (const float*)d_in[1];   // 256*255/2 fp32
    float* out = (float*)d_out;               // (B,) fp32

    const int B = in_sizes[0] / N128;

    // A (128*132) + double-buffered tau/col (1024) + sx (128) + idx (128)
    const size_t shmem = (size_t)(N128 * LDA + 2 * 4 * N128 + 2 * N128)
                         * sizeof(float);

    cudaFuncSetAttribute(pfaffian_kernel,
                         cudaFuncAttributeMaxDynamicSharedMemorySize,
                         (int)shmem);

    pfaffian_kernel<<<B, NTHR, shmem>>>(x, F, out);
}